// round 4
// baseline (speedup 1.0000x reference)
#include <cuda_runtime.h>
#include <cuda_bf16.h>

// Focal BCE with logits, mean-reduced.
//   loss(x,t) = a * (1-q)^gamma * (-ln q),  q = sigmoid((t==1)? x : -x),
//               a = (t==1)? ALPHA : 1-ALPHA
// Base-2 formulation (folds ln2 into the alpha constants):
//   u   = 2^(-log2e * y)                    (= e^-y)
//   spl = log2(1 + u)                       (= softplus(-y)/ln2 = -ln(q)/ln2)
//   w   = 2^(-g*log2e*y - g*spl)            (= (1-q)^gamma)
//   loss = (a*ln2) * w * spl
// => 3 MUFU + ~5 FP ops per element; kernel stays HBM-bound.
//
// Single-kernel reduction: blocks atomicAdd scaled partials into g_sum;
// a self-wrapping atomicInc counter identifies the last block, which writes
// d_out and resets g_sum so the kernel is graph-replay deterministic.

#define FOCAL_GAMMA 0.2f
#define FOCAL_ALPHA 0.6f
#define LOG2E 1.4426950408889634f
#define LN2   0.6931471805599453f

__device__ float        g_sum   = 0.0f;
__device__ unsigned int g_count = 0;

__device__ __forceinline__ float focal_elem(float x, int t) {
    bool pos = (t == 1);
    float y = pos ? x : -x;
    float a = pos ? (FOCAL_ALPHA * LN2) : ((1.0f - FOCAL_ALPHA) * LN2);
    float u   = exp2f(-LOG2E * y);                       // e^{-y}
    float spl = __log2f(1.0f + u);                       // -ln(q)/ln2
    float w   = exp2f(fmaf(-(FOCAL_GAMMA * LOG2E), y,
                           -FOCAL_GAMMA * spl));         // (1-q)^gamma
    return a * (w * spl);
}

__global__ void __launch_bounds__(256)
focal_main_kernel(const float4* __restrict__ x4,
                  const int4*  __restrict__ t4,
                  const float* __restrict__ x_scalar,
                  const int*   __restrict__ t_scalar,
                  float* __restrict__ out,
                  int n4, long long n_total, float inv_total) {
    float acc = 0.0f;
    int stride = gridDim.x * blockDim.x;
    int gid = blockIdx.x * blockDim.x + threadIdx.x;

    // Two float4/int4 pairs per iteration -> 4 independent LDG.E.128
    // in flight before any consumption (MLP >= 4).
    int i = gid;
    for (; i + stride < n4; i += 2 * stride) {
        float4 xa = x4[i];
        int4   ta = t4[i];
        float4 xb = x4[i + stride];
        int4   tb = t4[i + stride];
        acc += focal_elem(xa.x, ta.x);
        acc += focal_elem(xa.y, ta.y);
        acc += focal_elem(xa.z, ta.z);
        acc += focal_elem(xa.w, ta.w);
        acc += focal_elem(xb.x, tb.x);
        acc += focal_elem(xb.y, tb.y);
        acc += focal_elem(xb.z, tb.z);
        acc += focal_elem(xb.w, tb.w);
    }
    if (i < n4) {
        float4 xa = x4[i];
        int4   ta = t4[i];
        acc += focal_elem(xa.x, ta.x);
        acc += focal_elem(xa.y, ta.y);
        acc += focal_elem(xa.z, ta.z);
        acc += focal_elem(xa.w, ta.w);
    }

    // Scalar tail (n_total % 4 != 0).
    long long tail_start = (long long)n4 * 4;
    for (long long j = tail_start + gid; j < n_total; j += stride) {
        acc += focal_elem(x_scalar[j], t_scalar[j]);
    }

    // Intra-warp reduction
    #pragma unroll
    for (int off = 16; off > 0; off >>= 1)
        acc += __shfl_xor_sync(0xffffffffu, acc, off);

    __shared__ float warp_sums[8];
    int lane = threadIdx.x & 31;
    int wid  = threadIdx.x >> 5;
    if (lane == 0) warp_sums[wid] = acc;
    __syncthreads();

    if (wid == 0) {
        acc = (lane < (blockDim.x >> 5)) ? warp_sums[lane] : 0.0f;
        #pragma unroll
        for (int off = 4; off > 0; off >>= 1)
            acc += __shfl_xor_sync(0xffffffffu, acc, off);

        if (lane == 0) {
            atomicAdd(&g_sum, acc * inv_total);
            __threadfence();
            // atomicInc wraps to 0 after gridDim.x-1 -> counter self-resets
            // each graph replay.
            unsigned int prev = atomicInc(&g_count, gridDim.x - 1);
            if (prev == gridDim.x - 1) {
                // Last block: all other partials are visible (threadfence
                // before each counter increment).
                float total = *((volatile float*)&g_sum);
                out[0] = total;
                *((volatile float*)&g_sum) = 0.0f;   // reset for next replay
                __threadfence();
            }
        }
    }
}

extern "C" void kernel_launch(void* const* d_in, const int* in_sizes, int n_in,
                              void* d_out, int out_size) {
    const float* logits = (const float*)d_in[0];
    const int*   target = (const int*)d_in[1];
    float* out = (float*)d_out;

    long long n_total = (long long)in_sizes[0];
    int n4 = (int)(n_total / 4);
    float inv_total = (float)(1.0 / (double)n_total);

    // Full residency in one wave: 8 CTAs/SM x 148 SMs, 256 threads.
    int blocks = 148 * 8;
    long long max_useful = (n_total + 255) / 256;
    if ((long long)blocks > max_useful) blocks = (int)max_useful;
    if (blocks < 1) blocks = 1;

    focal_main_kernel<<<blocks, 256>>>(
        (const float4*)logits, (const int4*)target,
        logits, target, out, n4, n_total, inv_total);
}

// round 5
// speedup vs baseline: 1.0067x; 1.0067x over previous
#include <cuda_runtime.h>
#include <cuda_bf16.h>

// Focal BCE with logits, mean-reduced.
//   loss(x,t) = a * (1-q)^gamma * (-ln q),  q = sigmoid((t==1)? x : -x),
//               a = (t==1)? ALPHA : 1-ALPHA
// Base-2 formulation (folds ln2 into the alpha constants):
//   u   = 2^(-log2e * y)             (= e^-y)
//   spl = log2(1 + u)                (= -ln(q)/ln2)
//   w   = 2^(-g*log2e*y - g*spl)     (= (1-q)^gamma)
//   loss = (a*ln2) * w * spl
// => 3 MUFU + ~5 FP ops per element; kernel is LTS/HBM-bound.
//
// Single-kernel reduction with NO gpu-scope fences (a __threadfence here
// emits CCTL.IVALL = full L1D flush per block, measured ~1us regression in
// R4). Ordering is done with scoped atomics instead:
//   - partial sums: relaxed atomicAdd into g_sum
//   - counter:      atom.acq_rel.inc  (release: own add visible before inc;
//                                      acquire: last block sees all adds)
//   - last block:   ld.acquire of g_sum, writes d_out, relaxed reset of
//                   g_sum. Counter self-wraps -> graph-replay deterministic.

#define FOCAL_GAMMA 0.2f
#define FOCAL_ALPHA 0.6f
#define LOG2E 1.4426950408889634f
#define LN2   0.6931471805599453f

__device__ float        g_sum   = 0.0f;
__device__ unsigned int g_count = 0;

__device__ __forceinline__ float focal_elem(float x, int t) {
    bool pos = (t == 1);
    float y = pos ? x : -x;
    float a = pos ? (FOCAL_ALPHA * LN2) : ((1.0f - FOCAL_ALPHA) * LN2);
    float u   = exp2f(-LOG2E * y);                       // e^{-y}
    float spl = __log2f(1.0f + u);                       // -ln(q)/ln2
    float w   = exp2f(fmaf(-(FOCAL_GAMMA * LOG2E), y,
                           -FOCAL_GAMMA * spl));         // (1-q)^gamma
    return a * (w * spl);
}

__global__ void __launch_bounds__(256)
focal_main_kernel(const float4* __restrict__ x4,
                  const int4*  __restrict__ t4,
                  const float* __restrict__ x_scalar,
                  const int*   __restrict__ t_scalar,
                  float* __restrict__ out,
                  int n4, long long n_total, float inv_total) {
    float acc = 0.0f;
    int stride = gridDim.x * blockDim.x;
    int gid = blockIdx.x * blockDim.x + threadIdx.x;

    // Two float4/int4 pairs per iteration -> 4 independent LDG.E.128
    // in flight before any consumption. __ldcs: streaming (evict-first),
    // zero reuse.
    int i = gid;
    for (; i + stride < n4; i += 2 * stride) {
        float4 xa = __ldcs(&x4[i]);
        int4   ta = __ldcs(&t4[i]);
        float4 xb = __ldcs(&x4[i + stride]);
        int4   tb = __ldcs(&t4[i + stride]);
        acc += focal_elem(xa.x, ta.x);
        acc += focal_elem(xa.y, ta.y);
        acc += focal_elem(xa.z, ta.z);
        acc += focal_elem(xa.w, ta.w);
        acc += focal_elem(xb.x, tb.x);
        acc += focal_elem(xb.y, tb.y);
        acc += focal_elem(xb.z, tb.z);
        acc += focal_elem(xb.w, tb.w);
    }
    if (i < n4) {
        float4 xa = __ldcs(&x4[i]);
        int4   ta = __ldcs(&t4[i]);
        acc += focal_elem(xa.x, ta.x);
        acc += focal_elem(xa.y, ta.y);
        acc += focal_elem(xa.z, ta.z);
        acc += focal_elem(xa.w, ta.w);
    }

    // Scalar tail (n_total % 4 != 0; empty for this shape).
    long long tail_start = (long long)n4 * 4;
    for (long long j = tail_start + gid; j < n_total; j += stride) {
        acc += focal_elem(x_scalar[j], t_scalar[j]);
    }

    // Intra-warp reduction
    #pragma unroll
    for (int off = 16; off > 0; off >>= 1)
        acc += __shfl_xor_sync(0xffffffffu, acc, off);

    __shared__ float warp_sums[8];
    int lane = threadIdx.x & 31;
    int wid  = threadIdx.x >> 5;
    if (lane == 0) warp_sums[wid] = acc;
    __syncthreads();

    if (wid == 0) {
        acc = (lane < (blockDim.x >> 5)) ? warp_sums[lane] : 0.0f;
        #pragma unroll
        for (int off = 4; off > 0; off >>= 1)
            acc += __shfl_xor_sync(0xffffffffu, acc, off);

        if (lane == 0) {
            atomicAdd(&g_sum, acc * inv_total);   // relaxed partial
            unsigned int prev;
            // acq_rel: releases our add before the inc, acquires all
            // prior blocks' adds when we observe the final count.
            asm volatile("atom.acq_rel.gpu.global.inc.u32 %0, [%1], %2;"
                         : "=r"(prev)
                         : "l"(&g_count), "r"(gridDim.x - 1)
                         : "memory");
            if (prev == gridDim.x - 1) {
                float total;
                asm volatile("ld.acquire.gpu.global.f32 %0, [%1];"
                             : "=f"(total) : "l"(&g_sum) : "memory");
                out[0] = total;
                asm volatile("st.relaxed.gpu.global.f32 [%0], %1;"
                             :: "l"(&g_sum), "f"(0.0f) : "memory");
            }
        }
    }
}

extern "C" void kernel_launch(void* const* d_in, const int* in_sizes, int n_in,
                              void* d_out, int out_size) {
    const float* logits = (const float*)d_in[0];
    const int*   target = (const int*)d_in[1];
    float* out = (float*)d_out;

    long long n_total = (long long)in_sizes[0];
    int n4 = (int)(n_total / 4);
    float inv_total = (float)(1.0 / (double)n_total);

    // Full residency in one wave: 8 CTAs/SM x 148 SMs, 256 threads.
    int blocks = 148 * 8;
    long long max_useful = (n_total + 255) / 256;
    if ((long long)blocks > max_useful) blocks = (int)max_useful;
    if (blocks < 1) blocks = 1;

    focal_main_kernel<<<blocks, 256>>>(
        (const float4*)logits, (const int4*)target,
        logits, target, out, n4, n_total, inv_total);
}

// round 6
// speedup vs baseline: 1.0192x; 1.0124x over previous
#include <cuda_runtime.h>
#include <cuda_bf16.h>

// Focal BCE with logits, mean-reduced.
//   loss(x,t) = a * (1-q)^gamma * (-ln q),  q = sigmoid((t==1)? x : -x),
//               a = (t==1)? ALPHA : 1-ALPHA
// Base-2 formulation (folds ln2 into the alpha constants):
//   u   = 2^(-log2e * y)             (= e^-y)
//   spl = log2(1 + u)                (= -ln(q)/ln2)
//   w   = 2^(-g*log2e*y - g*spl)     (= (1-q)^gamma)
//   loss = (a*ln2) * w * spl
// => 3 MUFU + ~5 FP ops per element; kernel is HBM/LTS-bound.
//
// R6 = R3 load path (plain LDG.E.128 — best measured DRAM%, 74.6%;
// __ldcs evict-first measurably hurt streaming reads in R5) combined with
// the R5 single-launch epilogue (scoped atomics, no gpu-scope fence:
// __threadfence emits CCTL.IVALL = full L1D flush, measured ~1us in R4):
//   - partial sums: relaxed atomicAdd into g_sum
//   - counter:      atom.acq_rel.inc  (release own add / acquire all adds)
//   - last block:   ld.acquire g_sum -> d_out, relaxed reset of g_sum.
//     Counter self-wraps at gridDim.x -> graph-replay deterministic.

#define FOCAL_GAMMA 0.2f
#define FOCAL_ALPHA 0.6f
#define LOG2E 1.4426950408889634f
#define LN2   0.6931471805599453f

__device__ float        g_sum   = 0.0f;
__device__ unsigned int g_count = 0;

__device__ __forceinline__ float focal_elem(float x, int t) {
    bool pos = (t == 1);
    float y = pos ? x : -x;
    float a = pos ? (FOCAL_ALPHA * LN2) : ((1.0f - FOCAL_ALPHA) * LN2);
    float u   = exp2f(-LOG2E * y);                       // e^{-y}
    float spl = __log2f(1.0f + u);                       // -ln(q)/ln2
    float w   = exp2f(fmaf(-(FOCAL_GAMMA * LOG2E), y,
                           -FOCAL_GAMMA * spl));         // (1-q)^gamma
    return a * (w * spl);
}

__global__ void __launch_bounds__(256)
focal_main_kernel(const float4* __restrict__ x4,
                  const int4*  __restrict__ t4,
                  const float* __restrict__ x_scalar,
                  const int*   __restrict__ t_scalar,
                  float* __restrict__ out,
                  int n4, long long n_total, float inv_total) {
    float acc = 0.0f;
    int stride = gridDim.x * blockDim.x;
    int gid = blockIdx.x * blockDim.x + threadIdx.x;

    // Two float4/int4 pairs per iteration -> 4 independent LDG.E.128
    // in flight before any consumption (MLP >= 4). Plain loads: default
    // L2 policy streams at the highest measured DRAM%.
    int i = gid;
    for (; i + stride < n4; i += 2 * stride) {
        float4 xa = x4[i];
        int4   ta = t4[i];
        float4 xb = x4[i + stride];
        int4   tb = t4[i + stride];
        acc += focal_elem(xa.x, ta.x);
        acc += focal_elem(xa.y, ta.y);
        acc += focal_elem(xa.z, ta.z);
        acc += focal_elem(xa.w, ta.w);
        acc += focal_elem(xb.x, tb.x);
        acc += focal_elem(xb.y, tb.y);
        acc += focal_elem(xb.z, tb.z);
        acc += focal_elem(xb.w, tb.w);
    }
    if (i < n4) {
        float4 xa = x4[i];
        int4   ta = t4[i];
        acc += focal_elem(xa.x, ta.x);
        acc += focal_elem(xa.y, ta.y);
        acc += focal_elem(xa.z, ta.z);
        acc += focal_elem(xa.w, ta.w);
    }

    // Scalar tail (n_total % 4 != 0; empty for this shape).
    long long tail_start = (long long)n4 * 4;
    for (long long j = tail_start + gid; j < n_total; j += stride) {
        acc += focal_elem(x_scalar[j], t_scalar[j]);
    }

    // Intra-warp reduction
    #pragma unroll
    for (int off = 16; off > 0; off >>= 1)
        acc += __shfl_xor_sync(0xffffffffu, acc, off);

    __shared__ float warp_sums[8];
    int lane = threadIdx.x & 31;
    int wid  = threadIdx.x >> 5;
    if (lane == 0) warp_sums[wid] = acc;
    __syncthreads();

    if (wid == 0) {
        acc = (lane < (blockDim.x >> 5)) ? warp_sums[lane] : 0.0f;
        #pragma unroll
        for (int off = 4; off > 0; off >>= 1)
            acc += __shfl_xor_sync(0xffffffffu, acc, off);

        if (lane == 0) {
            atomicAdd(&g_sum, acc * inv_total);   // relaxed partial
            unsigned int prev;
            // acq_rel: releases our add before the inc, acquires all
            // prior blocks' adds when we observe the final count.
            asm volatile("atom.acq_rel.gpu.global.inc.u32 %0, [%1], %2;"
                         : "=r"(prev)
                         : "l"(&g_count), "r"(gridDim.x - 1)
                         : "memory");
            if (prev == gridDim.x - 1) {
                float total;
                asm volatile("ld.acquire.gpu.global.f32 %0, [%1];"
                             : "=f"(total) : "l"(&g_sum) : "memory");
                out[0] = total;
                asm volatile("st.relaxed.gpu.global.f32 [%0], %1;"
                             :: "l"(&g_sum), "f"(0.0f) : "memory");
            }
        }
    }
}

extern "C" void kernel_launch(void* const* d_in, const int* in_sizes, int n_in,
                              void* d_out, int out_size) {
    const float* logits = (const float*)d_in[0];
    const int*   target = (const int*)d_in[1];
    float* out = (float*)d_out;

    long long n_total = (long long)in_sizes[0];
    int n4 = (int)(n_total / 4);
    float inv_total = (float)(1.0 / (double)n_total);

    // Full residency in one wave: 8 CTAs/SM x 148 SMs, 256 threads.
    int blocks = 148 * 8;
    long long max_useful = (n_total + 255) / 256;
    if ((long long)blocks > max_useful) blocks = (int)max_useful;
    if (blocks < 1) blocks = 1;

    focal_main_kernel<<<blocks, 256>>>(
        (const float4*)logits, (const int4*)target,
        logits, target, out, n4, n_total, inv_total);
}

// round 7
// speedup vs baseline: 1.0822x; 1.0618x over previous
#include <cuda_runtime.h>
#include <cuda_bf16.h>

// Focal BCE with logits, mean-reduced.
//   loss(x,t) = a * (1-q)^gamma * (-ln q),  q = sigmoid((t==1)? x : -x),
//               a = (t==1)? ALPHA : 1-ALPHA
// Base-2 formulation (ln2 folded into alpha):
//   u   = 2^(-log2e * y)             (= e^-y)
//   spl = log2(1 + u)                (= -ln(q)/ln2)
//   w   = 2^(-g*log2e*y - g*spl)     (= (1-q)^gamma)
//   loss = (a*ln2) * w * spl
//
// R7: de-tail the one-wave persistent grid. A 1184-CTA static schedule ends
// when the SLOWEST CTA ends (L2-die variance + queue spread), leaving the
// wind-down phase bandwidth-starved. Instead: flat kernel, each thread does
// exactly 2 float4-pairs (4 front-batched LDG.E.128), grid = n4/512 = 20480
// CTAs. The HW work distributor backfills retiring CTAs -> load balancing
// at ~1us granularity, no global sync.
//
// Epilogue (proven R5/R6): relaxed atomicAdd partials into g_sum;
// atom.acq_rel.inc counter (self-wraps at gridDim.x -> replay-deterministic);
// last block ld.acquire's g_sum, writes d_out, relaxed-resets g_sum.
// No gpu-scope fence (CCTL.IVALL L1-flush measured ~1us in R4).

#define FOCAL_GAMMA 0.2f
#define FOCAL_ALPHA 0.6f
#define LOG2E 1.4426950408889634f
#define LN2   0.6931471805599453f

__device__ float        g_sum   = 0.0f;
__device__ unsigned int g_count = 0;

__device__ __forceinline__ float focal_elem(float x, int t) {
    bool pos = (t == 1);
    float y = pos ? x : -x;
    float a = pos ? (FOCAL_ALPHA * LN2) : ((1.0f - FOCAL_ALPHA) * LN2);
    float u   = exp2f(-LOG2E * y);                       // e^{-y}
    float spl = __log2f(1.0f + u);                       // -ln(q)/ln2
    float w   = exp2f(fmaf(-(FOCAL_GAMMA * LOG2E), y,
                           -FOCAL_GAMMA * spl));         // (1-q)^gamma
    return a * (w * spl);
}

__global__ void __launch_bounds__(256)
focal_flat_kernel(const float4* __restrict__ x4,
                  const int4*  __restrict__ t4,
                  const float* __restrict__ x_scalar,
                  const int*   __restrict__ t_scalar,
                  float* __restrict__ out,
                  int n4, long long n_total, float inv_total) {
    int tid = threadIdx.x;
    int i0 = blockIdx.x * 512 + tid;   // two contiguous 256-float4 segments
    int i1 = i0 + 256;

    float acc = 0.0f;
    // 4 independent LDG.E.128 issued up front (both guards uniform per-CTA
    // except the boundary block).
    if (i1 < n4) {
        float4 xa = x4[i0];
        int4   ta = t4[i0];
        float4 xb = x4[i1];
        int4   tb = t4[i1];
        acc += focal_elem(xa.x, ta.x);
        acc += focal_elem(xa.y, ta.y);
        acc += focal_elem(xa.z, ta.z);
        acc += focal_elem(xa.w, ta.w);
        acc += focal_elem(xb.x, tb.x);
        acc += focal_elem(xb.y, tb.y);
        acc += focal_elem(xb.z, tb.z);
        acc += focal_elem(xb.w, tb.w);
    } else if (i0 < n4) {
        float4 xa = x4[i0];
        int4   ta = t4[i0];
        acc += focal_elem(xa.x, ta.x);
        acc += focal_elem(xa.y, ta.y);
        acc += focal_elem(xa.z, ta.z);
        acc += focal_elem(xa.w, ta.w);
    }

    // Scalar tail (n_total % 4 != 0; empty for this shape). Block 0 only.
    if (blockIdx.x == 0) {
        long long tail_start = (long long)n4 * 4;
        for (long long j = tail_start + tid; j < n_total; j += 256) {
            acc += focal_elem(x_scalar[j], t_scalar[j]);
        }
    }

    // Intra-warp reduction
    #pragma unroll
    for (int off = 16; off > 0; off >>= 1)
        acc += __shfl_xor_sync(0xffffffffu, acc, off);

    __shared__ float warp_sums[8];
    int lane = tid & 31;
    int wid  = tid >> 5;
    if (lane == 0) warp_sums[wid] = acc;
    __syncthreads();

    if (wid == 0) {
        acc = (lane < 8) ? warp_sums[lane] : 0.0f;
        #pragma unroll
        for (int off = 4; off > 0; off >>= 1)
            acc += __shfl_xor_sync(0xffffffffu, acc, off);

        if (lane == 0) {
            atomicAdd(&g_sum, acc * inv_total);   // relaxed partial
            unsigned int prev;
            // acq_rel: releases our add before the inc, acquires all
            // prior blocks' adds when we observe the final count.
            asm volatile("atom.acq_rel.gpu.global.inc.u32 %0, [%1], %2;"
                         : "=r"(prev)
                         : "l"(&g_count), "r"(gridDim.x - 1)
                         : "memory");
            if (prev == gridDim.x - 1) {
                float total;
                asm volatile("ld.acquire.gpu.global.f32 %0, [%1];"
                             : "=f"(total) : "l"(&g_sum) : "memory");
                out[0] = total;
                asm volatile("st.relaxed.gpu.global.f32 [%0], %1;"
                             :: "l"(&g_sum), "f"(0.0f) : "memory");
            }
        }
    }
}

extern "C" void kernel_launch(void* const* d_in, const int* in_sizes, int n_in,
                              void* d_out, int out_size) {
    const float* logits = (const float*)d_in[0];
    const int*   target = (const int*)d_in[1];
    float* out = (float*)d_out;

    long long n_total = (long long)in_sizes[0];
    int n4 = (int)(n_total / 4);
    float inv_total = (float)(1.0 / (double)n_total);

    // One CTA per 512 float4s (2 per thread). For N*C = 41.94M: 20480 CTAs.
    int blocks = (n4 + 511) / 512;
    if (blocks < 1) blocks = 1;

    focal_flat_kernel<<<blocks, 256>>>(
        (const float4*)logits, (const int4*)target,
        logits, target, out, n4, n_total, inv_total);
}